// round 17
// baseline (speedup 1.0000x reference)
#include <cuda_runtime.h>
#include <cuda_bf16.h>
#include <math.h>

#define BATCH 32
#define HDIM 112
#define WDIM 112
#define CDIM 192
#define HW (HDIM*WDIM)          // 12544
#define C4 (CDIM/4)             // 48

// ---------------- scratch (device globals; no allocation) ----------------
__device__ float    g_sum[BATCH*CDIM];          // spatial sum per (b,c)
__device__ unsigned g_maxu[BATCH*CDIM];         // spatial max per (b,c), ordered-uint
__device__ float    g_scale[BATCH*CDIM];        // fused se*channel_att per (b,c)
__device__ float2   g_sp[BATCH*HW];             // per-pixel {avg_c, max_c}

__device__ __forceinline__ unsigned f2u_ord(float f) {
    unsigned u = __float_as_uint(f);
    return (u & 0x80000000u) ? ~u : (u | 0x80000000u);
}
__device__ __forceinline__ float u2f_ord(unsigned u) {
    return (u & 0x80000000u) ? __uint_as_float(u & 0x7fffffffu) : __uint_as_float(~u);
}
__device__ __forceinline__ float sigm(float v) { return 1.0f / (1.0f + expf(-v)); }
__device__ __forceinline__ float swishf(float v) { return v * sigm(v); }

// ---------------- kernel 0: init accumulators ----------------
__global__ void k_init() {
    int i = blockIdx.x * 256 + threadIdx.x;
    if (i < BATCH*CDIM) { g_sum[i] = 0.0f; g_maxu[i] = 0u; }
}

// ---------------- kernel 1: fused pools (one pass over x, 16-lane float4) --
// grid (56, B), block 256 (8 warps), two rows/block. Warp = PIXEL PAIR:
// lanes 0-15 own pixel A, lanes 16-31 own pixel B; each lane loads 3 float4
// (coalesced, no straddle). Pool was LDG-issue bound (38.5M LDG.64 at
// ~0.34/cyc/SM vs 0.55 floor): this halves load instructions AND shortens
// the butterfly to 4 steps (xor 8,4,2,1 within each 16-lane half).
__global__ void __launch_bounds__(256, 3) k_pool(const float* __restrict__ x) {
    int b = blockIdx.y;
    int h0 = blockIdx.x * 2;
    int warp = threadIdx.x >> 5, lane = threadIdx.x & 31;
    int l16 = lane & 15;
    int half = lane >> 4;                   // 0 = pixel A, 1 = pixel B

    __shared__ float    s_sum[CDIM];
    __shared__ unsigned s_max[CDIM];
    if (threadIdx.x < CDIM) { s_sum[threadIdx.x] = 0.0f; s_max[threadIdx.x] = 0u; }
    __syncthreads();

    float4 csum[3], cmax[3];
    #pragma unroll
    for (int j = 0; j < 3; j++) {
        csum[j] = make_float4(0.f, 0.f, 0.f, 0.f);
        cmax[j] = make_float4(-3.4e38f, -3.4e38f, -3.4e38f, -3.4e38f);
    }

    const float4* xbase = (const float4*)(x + (size_t)(b*HW + h0*WDIM) * CDIM);
    float2* spbase = g_sp + b*HW + h0*WDIM;

    // lane offset within the 96-float4 pair region
    int lofs = half * 48 + l16;

    float4 cur[3];
    int pr = warp;                          // pair index 0..111 (224 px / 2)
    #pragma unroll
    for (int j = 0; j < 3; j++)
        cur[j] = __ldcs(xbase + (size_t)pr*96 + lofs + 16*j);

    #pragma unroll
    for (int it = 0; it < 14; it++) {
        float4 nxt[3];
        if (it < 13) {
            #pragma unroll
            for (int j = 0; j < 3; j++)
                nxt[j] = __ldcs(xbase + (size_t)(pr+8)*96 + lofs + 16*j);
        }

        float ps = 0.0f, pm = -3.4e38f;
        #pragma unroll
        for (int j = 0; j < 3; j++) {
            float4 v = cur[j];
            csum[j].x += v.x; csum[j].y += v.y; csum[j].z += v.z; csum[j].w += v.w;
            cmax[j].x = fmaxf(cmax[j].x, v.x); cmax[j].y = fmaxf(cmax[j].y, v.y);
            cmax[j].z = fmaxf(cmax[j].z, v.z); cmax[j].w = fmaxf(cmax[j].w, v.w);
            ps += (v.x + v.y) + (v.z + v.w);
            pm = fmaxf(pm, fmaxf(fmaxf(v.x, v.y), fmaxf(v.z, v.w)));
        }

        // 4-step butterfly within each 16-lane half (both pixels at once)
        #pragma unroll
        for (int o = 8; o > 0; o >>= 1) {
            ps += __shfl_xor_sync(0xffffffffu, ps, o);
            pm = fmaxf(pm, __shfl_xor_sync(0xffffffffu, pm, o));
        }
        if (l16 == 0) spbase[2*pr + half] = make_float2(ps * (1.0f/192.0f), pm);

        #pragma unroll
        for (int j = 0; j < 3; j++) cur[j] = nxt[j];
        pr += 8;
    }

    // block-level channel combine: lane's vector j covers channels
    // 4*(l16 + 16*j) .. +3  (both halves hold the same channel groups)
    #pragma unroll
    for (int j = 0; j < 3; j++) {
        int c = 4*(l16 + 16*j);
        atomicAdd(&s_sum[c],   csum[j].x);
        atomicAdd(&s_sum[c+1], csum[j].y);
        atomicAdd(&s_sum[c+2], csum[j].z);
        atomicAdd(&s_sum[c+3], csum[j].w);
        atomicMax(&s_max[c],   f2u_ord(cmax[j].x));
        atomicMax(&s_max[c+1], f2u_ord(cmax[j].y));
        atomicMax(&s_max[c+2], f2u_ord(cmax[j].z));
        atomicMax(&s_max[c+3], f2u_ord(cmax[j].w));
    }
    __syncthreads();
    if (threadIdx.x < CDIM) {
        atomicAdd(&g_sum[b*CDIM + threadIdx.x], s_sum[threadIdx.x]);
        atomicMax(&g_maxu[b*CDIM + threadIdx.x], s_max[threadIdx.x]);
    }
}

// ---------------- kernel 2: SE + CBAM-channel MLPs, fused scale ----------------
// grid B, block 192
__global__ void k_mlp(const float* __restrict__ se_w1, const float* __restrict__ se_b1,
                      const float* __restrict__ se_w2, const float* __restrict__ se_b2,
                      const float* __restrict__ mlp_w1, const float* __restrict__ mlp_b1,
                      const float* __restrict__ mlp_w2, const float* __restrict__ mlp_b2) {
    int b = blockIdx.x, t = threadIdx.x;
    __shared__ float avg[CDIM], mx[CDIM], hse[12], ha[24], hm[24];

    avg[t] = g_sum[b*CDIM + t] * (1.0f/(float)HW);
    mx[t]  = u2f_ord(g_maxu[b*CDIM + t]);
    __syncthreads();

    if (t < 12) {
        float a = se_b1[t];
        for (int c = 0; c < CDIM; c++) a += avg[c] * se_w1[c*12 + t];
        hse[t] = swishf(a);
    } else if (t >= 32 && t < 56) {
        int j = t - 32;
        float a = mlp_b1[j], m = mlp_b1[j];
        for (int c = 0; c < CDIM; c++) {
            float w = mlp_w1[c*24 + j];
            a += avg[c]*w; m += mx[c]*w;
        }
        ha[j] = swishf(a); hm[j] = swishf(m);
    }
    __syncthreads();

    float s = se_b2[t];
    #pragma unroll
    for (int j = 0; j < 12; j++) s += hse[j] * se_w2[j*CDIM + t];
    float catt = 2.0f * mlp_b2[t];
    #pragma unroll
    for (int j = 0; j < 24; j++) catt += (ha[j] + hm[j]) * mlp_w2[j*CDIM + t];

    g_scale[b*CDIM + t] = sigm(s) * sigm(catt);
}

// ---------------- kernel 3: fused 7x7 conv + sigmoid + apply, 2 rows/block --
// grid (56, B), block (48, 8) = 384 threads. Tile 8x118 float2 of g_sp
// covers conv input for rows h0, h0+1; 224 threads compute both rows'
// spatial attention; then all 384 threads stream 2 rows of x -> out with
// plain float4 (R15: __ldcs/__stcs hurt here). Vs 1 row/block: 43% less
// tile traffic, half the barriers per streamed byte.
__global__ void k_apply(const float* __restrict__ x, float* __restrict__ out,
                        const float* __restrict__ conv_k, const float* __restrict__ conv_b) {
    int b = blockIdx.y, h0 = blockIdx.x * 2;
    int tid = threadIdx.y * C4 + threadIdx.x;

    __shared__ float2 tile[8][WDIM+6];     // rows h0-3..h0+4, cols -3..114
    __shared__ float  sa[2*WDIM];
    __shared__ float2 kk2[49];
    __shared__ float  kb;

    for (int i = tid; i < 8*(WDIM+6); i += 384) {
        int kh = i / (WDIM+6);
        int ww = i - kh*(WDIM+6);
        int gh = h0 + kh - 3, gw = ww - 3;
        float2 v = make_float2(0.0f, 0.0f);
        if (gh >= 0 && gh < HDIM && gw >= 0 && gw < WDIM)
            v = g_sp[b*HW + gh*WDIM + gw];
        tile[kh][ww] = v;
    }
    if (tid < 49) kk2[tid] = ((const float2*)conv_k)[tid];
    if (tid == 0) kb = conv_b[0];
    __syncthreads();

    if (tid < 2*WDIM) {
        int r = tid / WDIM;                // 0 or 1
        int c = tid - r*WDIM;
        float acc = kb;
        #pragma unroll
        for (int kh = 0; kh < 7; kh++)
            #pragma unroll
            for (int kw = 0; kw < 7; kw++) {
                float2 v = tile[r+kh][c+kw];
                float2 k = kk2[kh*7+kw];
                acc += v.x * k.x + v.y * k.y;
            }
        sa[tid] = sigm(acc);
    }
    __syncthreads();

    int c4 = threadIdx.x, ty = threadIdx.y;
    float4 sc = ((const float4*)(g_scale + b*CDIM))[c4];
    const float4* xp = (const float4*)x + (size_t)(b*HW + h0*WDIM) * C4;
    float4*       op = (float4*)out     + (size_t)(b*HW + h0*WDIM) * C4;

    #pragma unroll 7
    for (int p = ty; p < 2*WDIM; p += 8) {
        float s = sa[p];
        float4 v = xp[p*C4 + c4];
        v.x *= sc.x * s; v.y *= sc.y * s;
        v.z *= sc.z * s; v.w *= sc.w * s;
        op[p*C4 + c4] = v;
    }
}

// ---------------- launch ----------------
extern "C" void kernel_launch(void* const* d_in, const int* in_sizes, int n_in,
                              void* d_out, int out_size) {
    const float* x      = (const float*)d_in[0];
    const float* se_w1  = (const float*)d_in[1];
    const float* se_b1  = (const float*)d_in[2];
    const float* se_w2  = (const float*)d_in[3];
    const float* se_b2  = (const float*)d_in[4];
    const float* mlp_w1 = (const float*)d_in[5];
    const float* mlp_b1 = (const float*)d_in[6];
    const float* mlp_w2 = (const float*)d_in[7];
    const float* mlp_b2 = (const float*)d_in[8];
    const float* conv_k = (const float*)d_in[9];
    const float* conv_b = (const float*)d_in[10];
    float* out = (float*)d_out;

    k_init<<<(BATCH*CDIM + 255)/256, 256>>>();
    k_pool<<<dim3(HDIM/2, BATCH), 256>>>(x);
    k_mlp<<<BATCH, CDIM>>>(se_w1, se_b1, se_w2, se_b2, mlp_w1, mlp_b1, mlp_w2, mlp_b2);
    k_apply<<<dim3(HDIM/2, BATCH), dim3(C4, 8)>>>(x, out, conv_k, conv_b);
}